// round 1
// baseline (speedup 1.0000x reference)
#include <cuda_runtime.h>
#include <math.h>

// Problem dims (fixed by the reference)
#define SEQ   8192
#define KDIM  512
#define DDIM  512

// Scratch (allocation-free rule: __device__ globals)
__device__ float g_S [(size_t)SEQ * SEQ];    // 256 MB: attention logits / probs
__device__ float g_O1[(size_t)SEQ * KDIM];   // 16 MB: att @ V

// ---------------------------------------------------------------------------
// Tiled fp32 SGEMM: C[M,N] = alpha * A[M,K] * op(B)
//   TRANS_B=true : op(B) = B^T, B stored row-major [N,K]  (QK^T case)
//   TRANS_B=false: op(B) = B,   B stored row-major [K,N]
// BM=BN=128, BK=16, 256 threads, 8x8 register micro-tile per thread.
// All dims here are multiples of the tile sizes -> no bounds checks.
// ---------------------------------------------------------------------------
template <bool TRANS_B>
__global__ __launch_bounds__(256) void sgemm_kernel(
    const float* __restrict__ A,
    const float* __restrict__ B,
    float* __restrict__ C,
    int M, int N, int K, float alpha)
{
    constexpr int BM = 128, BN = 128, BK = 16, TM = 8, TN = 8;
    __shared__ float As[BK][BM + 4];
    __shared__ float Bs[BK][BN + 4];

    const int bx = blockIdx.x;          // N tile
    const int by = blockIdx.y;          // M tile
    const int tid = threadIdx.x;        // 0..255
    const int tx = tid & 15;            // 0..15 -> N micro-tile
    const int ty = tid >> 4;            // 0..15 -> M micro-tile

    float acc[TM][TN];
    #pragma unroll
    for (int i = 0; i < TM; i++)
        #pragma unroll
        for (int j = 0; j < TN; j++) acc[i][j] = 0.0f;

    for (int k0 = 0; k0 < K; k0 += BK) {
        // ---- load A tile: BM x BK, A is K-contiguous ----
        #pragma unroll
        for (int it = 0; it < 2; it++) {
            int idx  = tid + it * 256;          // 0..511 over BM*BK/4 float4s
            int row  = idx >> 2;                // 0..127
            int col4 = idx & 3;                 // 0..3
            float4 v = *(const float4*)(A + (size_t)(by * BM + row) * K + k0 + col4 * 4);
            As[col4 * 4 + 0][row] = v.x;
            As[col4 * 4 + 1][row] = v.y;
            As[col4 * 4 + 2][row] = v.z;
            As[col4 * 4 + 3][row] = v.w;
        }
        // ---- load B tile ----
        if (TRANS_B) {
            // B row-major [N,K]: tile rows bx*BN.., cols k0.. (K-contiguous)
            #pragma unroll
            for (int it = 0; it < 2; it++) {
                int idx  = tid + it * 256;
                int row  = idx >> 2;            // 0..127 (n within tile)
                int col4 = idx & 3;
                float4 v = *(const float4*)(B + (size_t)(bx * BN + row) * K + k0 + col4 * 4);
                Bs[col4 * 4 + 0][row] = v.x;
                Bs[col4 * 4 + 1][row] = v.y;
                Bs[col4 * 4 + 2][row] = v.z;
                Bs[col4 * 4 + 3][row] = v.w;
            }
        } else {
            // B row-major [K,N]: tile BK x BN, N-contiguous
            #pragma unroll
            for (int it = 0; it < 2; it++) {
                int idx = tid + it * 256;       // 0..511 over BK*BN/4 float4s
                int row = idx >> 5;             // 0..15 (k within tile)
                int c4  = idx & 31;             // 0..31
                float4 v = *(const float4*)(B + (size_t)(k0 + row) * N + bx * BN + c4 * 4);
                *(float4*)&Bs[row][c4 * 4] = v;
            }
        }
        __syncthreads();

        // ---- compute ----
        #pragma unroll
        for (int kk = 0; kk < BK; kk++) {
            float a_reg[TM], b_reg[TN];
            *(float4*)&a_reg[0] = *(const float4*)&As[kk][ty * TM + 0];
            *(float4*)&a_reg[4] = *(const float4*)&As[kk][ty * TM + 4];
            *(float4*)&b_reg[0] = *(const float4*)&Bs[kk][tx * TN + 0];
            *(float4*)&b_reg[4] = *(const float4*)&Bs[kk][tx * TN + 4];
            #pragma unroll
            for (int i = 0; i < TM; i++)
                #pragma unroll
                for (int j = 0; j < TN; j++)
                    acc[i][j] = fmaf(a_reg[i], b_reg[j], acc[i][j]);
        }
        __syncthreads();
    }

    // ---- writeback (vectorized) ----
    #pragma unroll
    for (int i = 0; i < TM; i++) {
        float* crow = C + (size_t)(by * BM + ty * TM + i) * N + bx * BN + tx * TN;
        float4 v0, v1;
        v0.x = alpha * acc[i][0]; v0.y = alpha * acc[i][1];
        v0.z = alpha * acc[i][2]; v0.w = alpha * acc[i][3];
        v1.x = alpha * acc[i][4]; v1.y = alpha * acc[i][5];
        v1.z = alpha * acc[i][6]; v1.w = alpha * acc[i][7];
        *(float4*)(crow + 0) = v0;
        *(float4*)(crow + 4) = v1;
    }
}

// ---------------------------------------------------------------------------
// Row softmax over SEQ=8192 columns. One CTA per row, 256 threads, whole row
// held in registers (8 float4 per thread) -> single read + single write.
// ---------------------------------------------------------------------------
__global__ __launch_bounds__(256) void softmax_rows_kernel(float* __restrict__ Sm)
{
    const int tid = threadIdx.x;
    float4* p = (float4*)(Sm + (size_t)blockIdx.x * SEQ);   // 2048 float4 per row

    float4 v[8];
    float mx = -1e30f;
    #pragma unroll
    for (int i = 0; i < 8; i++) {
        v[i] = p[tid + i * 256];
        mx = fmaxf(mx, fmaxf(fmaxf(v[i].x, v[i].y), fmaxf(v[i].z, v[i].w)));
    }

    __shared__ float red[8];
    #pragma unroll
    for (int o = 16; o > 0; o >>= 1) mx = fmaxf(mx, __shfl_xor_sync(0xffffffffu, mx, o));
    if ((tid & 31) == 0) red[tid >> 5] = mx;
    __syncthreads();
    mx = red[0];
    #pragma unroll
    for (int w = 1; w < 8; w++) mx = fmaxf(mx, red[w]);
    __syncthreads();   // red reused below

    float s = 0.0f;
    #pragma unroll
    for (int i = 0; i < 8; i++) {
        v[i].x = __expf(v[i].x - mx);
        v[i].y = __expf(v[i].y - mx);
        v[i].z = __expf(v[i].z - mx);
        v[i].w = __expf(v[i].w - mx);
        s += v[i].x + v[i].y + v[i].z + v[i].w;
    }
    #pragma unroll
    for (int o = 16; o > 0; o >>= 1) s += __shfl_xor_sync(0xffffffffu, s, o);
    if ((tid & 31) == 0) red[tid >> 5] = s;
    __syncthreads();
    s = red[0];
    #pragma unroll
    for (int w = 1; w < 8; w++) s += red[w];

    const float inv = 1.0f / s;
    #pragma unroll
    for (int i = 0; i < 8; i++) {
        v[i].x *= inv; v[i].y *= inv; v[i].z *= inv; v[i].w *= inv;
        p[tid + i * 256] = v[i];
    }
}

// ---------------------------------------------------------------------------
extern "C" void kernel_launch(void* const* d_in, const int* in_sizes, int n_in,
                              void* d_out, int out_size)
{
    const float* Q  = (const float*)d_in[0];
    const float* K  = (const float*)d_in[1];
    const float* V  = (const float*)d_in[2];
    const float* Wo = (const float*)d_in[3];
    float* out = (float*)d_out;

    float* Sbuf  = nullptr;
    float* O1buf = nullptr;
    cudaGetSymbolAddress((void**)&Sbuf,  g_S);
    cudaGetSymbolAddress((void**)&O1buf, g_O1);

    const float scale = 1.0f / sqrtf((float)KDIM);

    // 1) S = scale * Q @ K^T    [8192 x 8192]
    {
        dim3 grid(SEQ / 128, SEQ / 128);
        sgemm_kernel<true><<<grid, 256>>>(Q, K, Sbuf, SEQ, SEQ, KDIM, scale);
    }
    // 2) row softmax in place
    softmax_rows_kernel<<<SEQ, 256>>>(Sbuf);
    // 3) O1 = P @ V             [8192 x 512]
    {
        dim3 grid(KDIM / 128, SEQ / 128);
        sgemm_kernel<false><<<grid, 256>>>(Sbuf, V, O1buf, SEQ, KDIM, SEQ, 1.0f);
    }
    // 4) out = O1 @ Wo          [8192 x 512]
    {
        dim3 grid(DDIM / 128, SEQ / 128);
        sgemm_kernel<false><<<grid, 256>>>(O1buf, Wo, out, SEQ, DDIM, KDIM, 1.0f);
    }
}

// round 6
// speedup vs baseline: 1.9138x; 1.9138x over previous
#include <cuda_runtime.h>
#include <cuda_bf16.h>
#include <math.h>
#include <stdint.h>

#define SEQ   8192
#define KDIM  512
#define DDIM  512

// Scratch (__device__ globals; no allocation allowed)
__device__ float g_S  [(size_t)SEQ * SEQ];    // 256 MB logits/probs
__device__ float g_O1 [(size_t)SEQ * KDIM];   // 16 MB att@V
__device__ float g_Vt [(size_t)KDIM * SEQ];   // 16 MB V^T
__device__ float g_Wot[(size_t)DDIM * KDIM];  // 1 MB Wo^T

// ---------------------------------------------------------------------------
// bf16x3 GEMM on mma.sync (sm_80-class PTX; no tcgen05 — harness targets
// base compute_100 which rejects arch-accelerated instructions).
//   C[M,N] = alpha * A[M,K] * B^T   (A:[M,K], B:[N,K], both row-major)
// Split: hi = bf16(x), lo = bf16(x - hi);  D += Ahi*Bhi + Ahi*Blo + Alo*Bhi.
// CTA 128x128, BK=32, 8 warps x (64x32), 2-stage smem, reg-staged LDG.
// ---------------------------------------------------------------------------
#define BM 128
#define BN 128
#define BK 32
#define SKEW 40                       // bf16 elems per smem row (32 + 8 pad)
#define TILE_E (128 * SKEW)           // 5120 bf16 per tile
#define ST_AHI 0
#define ST_ALO TILE_E
#define ST_BHI (2 * TILE_E)
#define ST_BLO (3 * TILE_E)
#define STAGE_E (4 * TILE_E)          // 20480 bf16 per stage
#define GEMM_SMEM_BYTES (2 * STAGE_E * 2)   // 81920 B

__device__ __forceinline__ uint32_t smem_u32(const void* p) {
    uint32_t a;
    asm("{ .reg .u64 t; cvta.to.shared.u64 t, %1; cvt.u32.u64 %0, t; }" : "=r"(a) : "l"(p));
    return a;
}
__device__ __forceinline__ uint32_t pack_bf16(float a, float b) {
    __nv_bfloat162 h = __floats2bfloat162_rn(a, b);
    return *(uint32_t*)&h;
}
__device__ __forceinline__ void ldsm4(uint32_t& r0, uint32_t& r1, uint32_t& r2,
                                      uint32_t& r3, uint32_t addr) {
    asm volatile("ldmatrix.sync.aligned.m8n8.x4.shared.b16 {%0,%1,%2,%3}, [%4];"
                 : "=r"(r0), "=r"(r1), "=r"(r2), "=r"(r3) : "r"(addr));
}
__device__ __forceinline__ void mma16816(float* d, const uint32_t* a, const uint32_t* b) {
    asm volatile(
        "mma.sync.aligned.m16n8k16.row.col.f32.bf16.bf16.f32 "
        "{%0,%1,%2,%3}, {%4,%5,%6,%7}, {%8,%9}, {%0,%1,%2,%3};"
        : "+f"(d[0]), "+f"(d[1]), "+f"(d[2]), "+f"(d[3])
        : "r"(a[0]), "r"(a[1]), "r"(a[2]), "r"(a[3]), "r"(b[0]), "r"(b[1]));
}

__global__ __launch_bounds__(256, 1) void bf16x3_mma_gemm(
    const float* __restrict__ A, const float* __restrict__ B, float* __restrict__ C,
    int M, int N, int K, float alpha)
{
    extern __shared__ __nv_bfloat16 sm[];
    const uint32_t smbase = smem_u32(sm);
    const int tid  = threadIdx.x;
    const int wid  = tid >> 5;
    const int lane = tid & 31;
    const int wm   = (wid >> 2) * 64;   // warp M offset (0 or 64)
    const int wn   = (wid & 3) * 32;    // warp N offset (0,32,64,96)

    const float* Ab = A + (size_t)blockIdx.y * BM * K;
    const float* Bb = B + (size_t)blockIdx.x * BN * K;

    float acc[4][4][4];
    #pragma unroll
    for (int i = 0; i < 4; i++)
        #pragma unroll
        for (int j = 0; j < 4; j++)
            #pragma unroll
            for (int r = 0; r < 4; r++) acc[i][j][r] = 0.0f;

    // staging-load mapping: per it, row = tid>>3 + 32*it, float4 index = tid&7
    const int row0 = tid >> 3;
    const int k4   = tid & 7;
    float4 av[4], bv[4];

    // ldmatrix per-thread address components
    const int rA   = lane & 15;
    const int colS = (lane >> 4) << 3;   // 0 or 8

    const int NC = K / BK;

    // ---- lambdas ----
    auto LDG = [&](int c) {
        #pragma unroll
        for (int it = 0; it < 4; it++) {
            const size_t ro = (size_t)(row0 + 32 * it) * K + (size_t)c * BK + k4 * 4;
            av[it] = *(const float4*)(Ab + ro);
            bv[it] = *(const float4*)(Bb + ro);
        }
    };
    auto STS = [&](int s) {
        __nv_bfloat16* st = sm + s * STAGE_E;
        #pragma unroll
        for (int it = 0; it < 4; it++) {
            const int off = (row0 + 32 * it) * SKEW + k4 * 4;
            {
                float4 v = av[it];
                float h0 = __bfloat162float(__float2bfloat16_rn(v.x));
                float h1 = __bfloat162float(__float2bfloat16_rn(v.y));
                float h2 = __bfloat162float(__float2bfloat16_rn(v.z));
                float h3 = __bfloat162float(__float2bfloat16_rn(v.w));
                *(uint2*)(st + ST_AHI + off) =
                    make_uint2(pack_bf16(h0, h1), pack_bf16(h2, h3));
                *(uint2*)(st + ST_ALO + off) =
                    make_uint2(pack_bf16(v.x - h0, v.y - h1), pack_bf16(v.z - h2, v.w - h3));
            }
            {
                float4 v = bv[it];
                float h0 = __bfloat162float(__float2bfloat16_rn(v.x));
                float h1 = __bfloat162float(__float2bfloat16_rn(v.y));
                float h2 = __bfloat162float(__float2bfloat16_rn(v.z));
                float h3 = __bfloat162float(__float2bfloat16_rn(v.w));
                *(uint2*)(st + ST_BHI + off) =
                    make_uint2(pack_bf16(h0, h1), pack_bf16(h2, h3));
                *(uint2*)(st + ST_BLO + off) =
                    make_uint2(pack_bf16(v.x - h0, v.y - h1), pack_bf16(v.z - h2, v.w - h3));
            }
        }
    };
    auto MMA = [&](int s) {
        const uint32_t base = smbase + (uint32_t)(s * STAGE_E) * 2;
        #pragma unroll
        for (int ks = 0; ks < 2; ks++) {
            const int col = ks * 16 + colS;
            uint32_t ah[4][4], al[4][4], bh[4][2], bl[4][2];
            #pragma unroll
            for (int mi = 0; mi < 4; mi++) {
                const uint32_t ro = (uint32_t)((wm + mi * 16 + rA) * SKEW + col) * 2;
                ldsm4(ah[mi][0], ah[mi][1], ah[mi][2], ah[mi][3],
                      base + (uint32_t)ST_AHI * 2 + ro);
                ldsm4(al[mi][0], al[mi][1], al[mi][2], al[mi][3],
                      base + (uint32_t)ST_ALO * 2 + ro);
            }
            #pragma unroll
            for (int p = 0; p < 2; p++) {
                const uint32_t ro = (uint32_t)((wn + p * 16 + rA) * SKEW + col) * 2;
                uint32_t r0, r1, r2, r3;
                ldsm4(r0, r1, r2, r3, base + (uint32_t)ST_BHI * 2 + ro);
                bh[2 * p][0] = r0; bh[2 * p][1] = r2;
                bh[2 * p + 1][0] = r1; bh[2 * p + 1][1] = r3;
                ldsm4(r0, r1, r2, r3, base + (uint32_t)ST_BLO * 2 + ro);
                bl[2 * p][0] = r0; bl[2 * p][1] = r2;
                bl[2 * p + 1][0] = r1; bl[2 * p + 1][1] = r3;
            }
            #pragma unroll
            for (int mi = 0; mi < 4; mi++)
                #pragma unroll
                for (int nj = 0; nj < 4; nj++) {
                    mma16816(acc[mi][nj], ah[mi], bh[nj]);
                    mma16816(acc[mi][nj], ah[mi], bl[nj]);
                    mma16816(acc[mi][nj], al[mi], bh[nj]);
                }
        }
    };

    // ---- pipeline: LDG(c+1) | MMA(c) | STS(c+1) | sync ----
    LDG(0);
    STS(0);
    __syncthreads();
    for (int c = 0; c < NC; c++) {
        const int s = c & 1;
        if (c + 1 < NC) LDG(c + 1);
        MMA(s);
        if (c + 1 < NC) STS(s ^ 1);
        __syncthreads();
    }

    // ---- epilogue ----
    #pragma unroll
    for (int mi = 0; mi < 4; mi++) {
        #pragma unroll
        for (int nj = 0; nj < 4; nj++) {
            const int r0  = blockIdx.y * BM + wm + mi * 16 + (lane >> 2);
            const int col = blockIdx.x * BN + wn + nj * 8 + 2 * (lane & 3);
            float2 v0 = make_float2(alpha * acc[mi][nj][0], alpha * acc[mi][nj][1]);
            float2 v1 = make_float2(alpha * acc[mi][nj][2], alpha * acc[mi][nj][3]);
            *(float2*)(C + (size_t)r0 * N + col)       = v0;
            *(float2*)(C + (size_t)(r0 + 8) * N + col) = v1;
        }
    }
}

// ---------------------------------------------------------------------------
// Transpose: out[c][r] = in[r][c], in is RxC. 32x32 tiles, block (32,8).
// ---------------------------------------------------------------------------
__global__ __launch_bounds__(256) void transpose_kernel(
    const float* __restrict__ in, float* __restrict__ out, int R, int C)
{
    __shared__ float t[32][33];
    const int bx = blockIdx.x * 32;
    const int by = blockIdx.y * 32;
    #pragma unroll
    for (int j = threadIdx.y; j < 32; j += 8)
        t[j][threadIdx.x] = in[(size_t)(by + j) * C + bx + threadIdx.x];
    __syncthreads();
    #pragma unroll
    for (int j = threadIdx.y; j < 32; j += 8)
        out[(size_t)(bx + j) * R + by + threadIdx.x] = t[threadIdx.x][j];
}

// ---------------------------------------------------------------------------
// Row softmax over SEQ columns. One CTA/row, 256 threads, row in registers.
// ---------------------------------------------------------------------------
__global__ __launch_bounds__(256) void softmax_rows_kernel(float* __restrict__ Sm)
{
    const int tid = threadIdx.x;
    float4* p = (float4*)(Sm + (size_t)blockIdx.x * SEQ);

    float4 v[8];
    float mx = -1e30f;
    #pragma unroll
    for (int i = 0; i < 8; i++) {
        v[i] = p[tid + i * 256];
        mx = fmaxf(mx, fmaxf(fmaxf(v[i].x, v[i].y), fmaxf(v[i].z, v[i].w)));
    }
    __shared__ float red[8];
    #pragma unroll
    for (int o = 16; o > 0; o >>= 1) mx = fmaxf(mx, __shfl_xor_sync(0xffffffffu, mx, o));
    if ((tid & 31) == 0) red[tid >> 5] = mx;
    __syncthreads();
    mx = red[0];
    #pragma unroll
    for (int w = 1; w < 8; w++) mx = fmaxf(mx, red[w]);
    __syncthreads();

    float s = 0.0f;
    #pragma unroll
    for (int i = 0; i < 8; i++) {
        v[i].x = __expf(v[i].x - mx);
        v[i].y = __expf(v[i].y - mx);
        v[i].z = __expf(v[i].z - mx);
        v[i].w = __expf(v[i].w - mx);
        s += v[i].x + v[i].y + v[i].z + v[i].w;
    }
    #pragma unroll
    for (int o = 16; o > 0; o >>= 1) s += __shfl_xor_sync(0xffffffffu, s, o);
    if ((tid & 31) == 0) red[tid >> 5] = s;
    __syncthreads();
    s = red[0];
    #pragma unroll
    for (int w = 1; w < 8; w++) s += red[w];

    const float inv = 1.0f / s;
    #pragma unroll
    for (int i = 0; i < 8; i++) {
        v[i].x *= inv; v[i].y *= inv; v[i].z *= inv; v[i].w *= inv;
        p[tid + i * 256] = v[i];
    }
}

// ---------------------------------------------------------------------------
extern "C" void kernel_launch(void* const* d_in, const int* in_sizes, int n_in,
                              void* d_out, int out_size)
{
    const float* Q  = (const float*)d_in[0];
    const float* Km = (const float*)d_in[1];
    const float* V  = (const float*)d_in[2];
    const float* Wo = (const float*)d_in[3];
    float* out = (float*)d_out;

    float *Sbuf, *O1, *Vt, *Wot;
    cudaGetSymbolAddress((void**)&Sbuf, g_S);
    cudaGetSymbolAddress((void**)&O1,   g_O1);
    cudaGetSymbolAddress((void**)&Vt,   g_Vt);
    cudaGetSymbolAddress((void**)&Wot,  g_Wot);

    cudaFuncSetAttribute(bf16x3_mma_gemm,
                         cudaFuncAttributeMaxDynamicSharedMemorySize, GEMM_SMEM_BYTES);

    const float scale = 1.0f / sqrtf((float)KDIM);

    // Pre-transpose V and Wo so every GEMM is C = A * B^T (K-major B)
    transpose_kernel<<<dim3(KDIM / 32, SEQ / 32), dim3(32, 8)>>>(V, Vt, SEQ, KDIM);
    transpose_kernel<<<dim3(DDIM / 32, KDIM / 32), dim3(32, 8)>>>(Wo, Wot, KDIM, DDIM);

    // 1) S = scale * Q @ K^T
    bf16x3_mma_gemm<<<dim3(SEQ / BN, SEQ / BM), 256, GEMM_SMEM_BYTES>>>(
        Q, Km, Sbuf, SEQ, SEQ, KDIM, scale);
    // 2) softmax rows in place
    softmax_rows_kernel<<<SEQ, 256>>>(Sbuf);
    // 3) O1 = P @ V   (B = V^T)
    bf16x3_mma_gemm<<<dim3(KDIM / BN, SEQ / BM), 256, GEMM_SMEM_BYTES>>>(
        Sbuf, Vt, O1, SEQ, KDIM, SEQ, 1.0f);
    // 4) out = O1 @ Wo  (B = Wo^T)
    bf16x3_mma_gemm<<<dim3(DDIM / BN, SEQ / BM), 256, GEMM_SMEM_BYTES>>>(
        O1, Wot, out, SEQ, DDIM, KDIM, 1.0f);
}

// round 8
// speedup vs baseline: 1.9633x; 1.0259x over previous
#include <cuda_runtime.h>
#include <cuda_bf16.h>
#include <math.h>
#include <stdint.h>

#define SEQ   8192
#define KDIM  512
#define DDIM  512

typedef __nv_bfloat16 bf16;
typedef __nv_bfloat162 bf162;

// ---------------- scratch (__device__ globals; no allocation allowed) -------
__device__ bf16  g_Phi [(size_t)SEQ * SEQ];    // 128 MB  exp(S) hi
__device__ bf16  g_Plo [(size_t)SEQ * SEQ];    // 128 MB  exp(S) lo
__device__ bf16  g_Qhi [(size_t)SEQ * KDIM];
__device__ bf16  g_Qlo [(size_t)SEQ * KDIM];
__device__ bf16  g_Khi [(size_t)SEQ * KDIM];
__device__ bf16  g_Klo [(size_t)SEQ * KDIM];
__device__ bf16  g_Vthi[(size_t)KDIM * SEQ];   // V^T hi
__device__ bf16  g_Vtlo[(size_t)KDIM * SEQ];
__device__ bf16  g_Wothi[(size_t)DDIM * KDIM]; // Wo^T hi
__device__ bf16  g_Wotlo[(size_t)DDIM * KDIM];
__device__ bf16  g_O1hi[(size_t)SEQ * KDIM];
__device__ bf16  g_O1lo[(size_t)SEQ * KDIM];
__device__ float g_rowsum[SEQ];

// ---------------------------------------------------------------------------
// bf16x3 GEMM on mma.sync + cp.async:  C = A * B^T
//   A given as pre-split hi/lo bf16 [M,K]; B as hi/lo bf16 [N,K].
//   acc += Ahi*Bhi + Ahi*Blo + Alo*Bhi  (fp32 accum)
// CTA 128x128, BK=32, 8 warps x (64x32), 4-stage cp.async pipeline.
// Epilogues: PLAIN fp32 | EXP->bf16 split + rowsum atomics | SCALE->bf16 split
// ---------------------------------------------------------------------------
#define BM 128
#define BN 128
#define BK 32
#define SKEW 40                          // bf16 per smem row (32 data + 8 pad)
#define OFF_AHI 0
#define OFF_ALO (128 * SKEW * 2)         // bytes
#define OFF_BHI (2 * 128 * SKEW * 2)
#define OFF_BLO (3 * 128 * SKEW * 2)
#define STAGE_BYTES (4 * 128 * SKEW * 2) // 40960
#define NSTAGE 4
#define GEMM_SMEM (NSTAGE * STAGE_BYTES) // 163840

#define EPI_PLAIN 0
#define EPI_EXP   1
#define EPI_SCALE 2

__device__ __forceinline__ uint32_t smem_u32(const void* p) {
    uint32_t a;
    asm("{ .reg .u64 t; cvta.to.shared.u64 t, %1; cvt.u32.u64 %0, t; }" : "=r"(a) : "l"(p));
    return a;
}
__device__ __forceinline__ void cpa16(uint32_t dst, const void* src) {
    asm volatile("cp.async.cg.shared.global [%0], [%1], 16;" :: "r"(dst), "l"(src));
}
__device__ __forceinline__ void ldsm4(uint32_t& r0, uint32_t& r1, uint32_t& r2,
                                      uint32_t& r3, uint32_t addr) {
    asm volatile("ldmatrix.sync.aligned.m8n8.x4.shared.b16 {%0,%1,%2,%3}, [%4];"
                 : "=r"(r0), "=r"(r1), "=r"(r2), "=r"(r3) : "r"(addr));
}
__device__ __forceinline__ void mma16816(float* d, const uint32_t* a, const uint32_t* b) {
    asm volatile(
        "mma.sync.aligned.m16n8k16.row.col.f32.bf16.bf16.f32 "
        "{%0,%1,%2,%3}, {%4,%5,%6,%7}, {%8,%9}, {%0,%1,%2,%3};"
        : "+f"(d[0]), "+f"(d[1]), "+f"(d[2]), "+f"(d[3])
        : "r"(a[0]), "r"(a[1]), "r"(a[2]), "r"(a[3]), "r"(b[0]), "r"(b[1]));
}

template <int EPI>
__global__ __launch_bounds__(256, 1) void gemm_bf16x3(
    const bf16* __restrict__ Ahi, const bf16* __restrict__ Alo,
    const bf16* __restrict__ Bhi, const bf16* __restrict__ Blo,
    float* __restrict__ Cf, bf16* __restrict__ Chi, bf16* __restrict__ Clo,
    float* __restrict__ rowsum, int K, int N, float alpha)
{
    extern __shared__ char sm[];
    const uint32_t smbase = smem_u32(sm);
    const int tid  = threadIdx.x;
    const int wid  = tid >> 5;
    const int lane = tid & 31;
    const int wm   = (wid >> 2) * 64;
    const int wn   = (wid & 3) * 32;

    const size_t aoff = (size_t)blockIdx.y * BM * K;
    const size_t boff = (size_t)blockIdx.x * BN * K;
    const bf16* Ah = Ahi + aoff;  const bf16* Al = Alo + aoff;
    const bf16* Bh = Bhi + boff;  const bf16* Bl = Blo + boff;

    float acc[4][4][4];
    #pragma unroll
    for (int i = 0; i < 4; i++)
        #pragma unroll
        for (int j = 0; j < 4; j++)
            #pragma unroll
            for (int r = 0; r < 4; r++) acc[i][j][r] = 0.0f;

    const int NC = K / BK;

    auto FILL = [&](int c, int s) {
        const uint32_t sb = smbase + (uint32_t)s * STAGE_BYTES;
        #pragma unroll
        for (int i = 0; i < 2; i++) {
            const int idx = tid + i * 256;       // 0..511
            const int row = idx >> 2;            // 0..127
            const int ch  = idx & 3;             // 16B chunk within 64B row
            const uint32_t d = (uint32_t)(row * SKEW + ch * 8) * 2;
            const size_t go = (size_t)row * K + (size_t)c * BK + ch * 8;
            cpa16(sb + OFF_AHI + d, Ah + go);
            cpa16(sb + OFF_ALO + d, Al + go);
            cpa16(sb + OFF_BHI + d, Bh + go);
            cpa16(sb + OFF_BLO + d, Bl + go);
        }
    };

    const int rA   = lane & 15;
    const int colS = (lane >> 4) << 3;

    auto MMA = [&](int s) {
        const uint32_t base = smbase + (uint32_t)s * STAGE_BYTES;
        #pragma unroll
        for (int ks = 0; ks < 2; ks++) {
            const int col = ks * 16 + colS;
            uint32_t ah[4][4], al[4][4], bh[4][2], bl[4][2];
            #pragma unroll
            for (int mi = 0; mi < 4; mi++) {
                const uint32_t ro = (uint32_t)((wm + mi * 16 + rA) * SKEW + col) * 2;
                ldsm4(ah[mi][0], ah[mi][1], ah[mi][2], ah[mi][3], base + OFF_AHI + ro);
                ldsm4(al[mi][0], al[mi][1], al[mi][2], al[mi][3], base + OFF_ALO + ro);
            }
            #pragma unroll
            for (int p = 0; p < 2; p++) {
                const uint32_t ro = (uint32_t)((wn + p * 16 + rA) * SKEW + col) * 2;
                uint32_t r0, r1, r2, r3;
                ldsm4(r0, r1, r2, r3, base + OFF_BHI + ro);
                bh[2 * p][0] = r0; bh[2 * p][1] = r2;
                bh[2 * p + 1][0] = r1; bh[2 * p + 1][1] = r3;
                ldsm4(r0, r1, r2, r3, base + OFF_BLO + ro);
                bl[2 * p][0] = r0; bl[2 * p][1] = r2;
                bl[2 * p + 1][0] = r1; bl[2 * p + 1][1] = r3;
            }
            #pragma unroll
            for (int mi = 0; mi < 4; mi++)
                #pragma unroll
                for (int nj = 0; nj < 4; nj++) {
                    mma16816(acc[mi][nj], ah[mi], bh[nj]);
                    mma16816(acc[mi][nj], ah[mi], bl[nj]);
                    mma16816(acc[mi][nj], al[mi], bh[nj]);
                }
        }
    };

    // ---- 4-stage pipeline; one commit_group per fill slot (empty ok) ----
    FILL(0, 0); asm volatile("cp.async.commit_group;");
    FILL(1, 1); asm volatile("cp.async.commit_group;");
    FILL(2, 2); asm volatile("cp.async.commit_group;");

    for (int c = 0; c < NC; c++) {
        asm volatile("cp.async.wait_group 2;");
        __syncthreads();
        MMA(c & 3);
        if (c + 3 < NC) FILL(c + 3, (c + 3) & 3);
        asm volatile("cp.async.commit_group;");
    }

    // ---- epilogue ----
    #pragma unroll
    for (int mi = 0; mi < 4; mi++) {
        const int r0 = blockIdx.y * BM + wm + mi * 16 + (lane >> 2);
        float rs0 = 0.0f, rs1 = 0.0f;
        float inv0 = 1.0f, inv1 = 1.0f;
        if (EPI == EPI_SCALE) {
            inv0 = 1.0f / rowsum[r0];
            inv1 = 1.0f / rowsum[r0 + 8];
        }
        #pragma unroll
        for (int nj = 0; nj < 4; nj++) {
            const int col = blockIdx.x * BN + wn + nj * 8 + 2 * (lane & 3);
            if (EPI == EPI_PLAIN) {
                *(float2*)(Cf + (size_t)r0 * N + col) =
                    make_float2(acc[mi][nj][0], acc[mi][nj][1]);
                *(float2*)(Cf + (size_t)(r0 + 8) * N + col) =
                    make_float2(acc[mi][nj][2], acc[mi][nj][3]);
            } else if (EPI == EPI_EXP) {
                float e0 = __expf(alpha * acc[mi][nj][0]);
                float e1 = __expf(alpha * acc[mi][nj][1]);
                float e2 = __expf(alpha * acc[mi][nj][2]);
                float e3 = __expf(alpha * acc[mi][nj][3]);
                bf16 h0 = __float2bfloat16_rn(e0), h1 = __float2bfloat16_rn(e1);
                bf16 h2 = __float2bfloat16_rn(e2), h3 = __float2bfloat16_rn(e3);
                *(bf162*)(Chi + (size_t)r0 * N + col) = bf162(h0, h1);
                *(bf162*)(Chi + (size_t)(r0 + 8) * N + col) = bf162(h2, h3);
                *(bf162*)(Clo + (size_t)r0 * N + col) =
                    bf162(__float2bfloat16_rn(e0 - __bfloat162float(h0)),
                          __float2bfloat16_rn(e1 - __bfloat162float(h1)));
                *(bf162*)(Clo + (size_t)(r0 + 8) * N + col) =
                    bf162(__float2bfloat16_rn(e2 - __bfloat162float(h2)),
                          __float2bfloat16_rn(e3 - __bfloat162float(h3)));
                rs0 += e0 + e1;  rs1 += e2 + e3;
            } else { // EPI_SCALE
                float v0 = acc[mi][nj][0] * inv0, v1 = acc[mi][nj][1] * inv0;
                float v2 = acc[mi][nj][2] * inv1, v3 = acc[mi][nj][3] * inv1;
                bf16 h0 = __float2bfloat16_rn(v0), h1 = __float2bfloat16_rn(v1);
                bf16 h2 = __float2bfloat16_rn(v2), h3 = __float2bfloat16_rn(v3);
                *(bf162*)(Chi + (size_t)r0 * N + col) = bf162(h0, h1);
                *(bf162*)(Chi + (size_t)(r0 + 8) * N + col) = bf162(h2, h3);
                *(bf162*)(Clo + (size_t)r0 * N + col) =
                    bf162(__float2bfloat16_rn(v0 - __bfloat162float(h0)),
                          __float2bfloat16_rn(v1 - __bfloat162float(h1)));
                *(bf162*)(Clo + (size_t)(r0 + 8) * N + col) =
                    bf162(__float2bfloat16_rn(v2 - __bfloat162float(h2)),
                          __float2bfloat16_rn(v3 - __bfloat162float(h3)));
            }
        }
        if (EPI == EPI_EXP) {
            rs0 += __shfl_xor_sync(0xffffffffu, rs0, 1);
            rs0 += __shfl_xor_sync(0xffffffffu, rs0, 2);
            rs1 += __shfl_xor_sync(0xffffffffu, rs1, 1);
            rs1 += __shfl_xor_sync(0xffffffffu, rs1, 2);
            if ((lane & 3) == 0) {
                atomicAdd(rowsum + r0, rs0);
                atomicAdd(rowsum + r0 + 8, rs1);
            }
        }
    }
}

// ---------------------------------------------------------------------------
// fp32 -> bf16 hi/lo elementwise split (vectorized)
// ---------------------------------------------------------------------------
__global__ __launch_bounds__(256) void split_kernel(
    const float* __restrict__ in, bf16* __restrict__ hi, bf16* __restrict__ lo)
{
    const size_t i = (size_t)blockIdx.x * 256 + threadIdx.x;
    float4 v = ((const float4*)in)[i];
    bf16 h0 = __float2bfloat16_rn(v.x), h1 = __float2bfloat16_rn(v.y);
    bf16 h2 = __float2bfloat16_rn(v.z), h3 = __float2bfloat16_rn(v.w);
    ((bf162*)hi)[2 * i]     = bf162(h0, h1);
    ((bf162*)hi)[2 * i + 1] = bf162(h2, h3);
    ((bf162*)lo)[2 * i] =
        bf162(__float2bfloat16_rn(v.x - __bfloat162float(h0)),
              __float2bfloat16_rn(v.y - __bfloat162float(h1)));
    ((bf162*)lo)[2 * i + 1] =
        bf162(__float2bfloat16_rn(v.z - __bfloat162float(h2)),
              __float2bfloat16_rn(v.w - __bfloat162float(h3)));
}

// ---------------------------------------------------------------------------
// Transpose + split: in [R,C] fp32 -> out^T [C,R] bf16 hi/lo
// ---------------------------------------------------------------------------
__global__ __launch_bounds__(256) void transpose_split_kernel(
    const float* __restrict__ in, bf16* __restrict__ ohi, bf16* __restrict__ olo,
    int R, int C)
{
    __shared__ float t[32][33];
    const int bx = blockIdx.x * 32;   // C offset
    const int by = blockIdx.y * 32;   // R offset
    #pragma unroll
    for (int j = threadIdx.y; j < 32; j += 8)
        t[j][threadIdx.x] = in[(size_t)(by + j) * C + bx + threadIdx.x];
    __syncthreads();
    #pragma unroll
    for (int j = threadIdx.y; j < 32; j += 8) {
        const float v = t[threadIdx.x][j];
        const size_t o = (size_t)(bx + j) * R + by + threadIdx.x;
        const bf16 h = __float2bfloat16_rn(v);
        ohi[o] = h;
        olo[o] = __float2bfloat16_rn(v - __bfloat162float(h));
    }
}

__global__ void zero_rowsum_kernel(float* __restrict__ rs)
{
    rs[blockIdx.x * 256 + threadIdx.x] = 0.0f;
}

// ---------------------------------------------------------------------------
extern "C" void kernel_launch(void* const* d_in, const int* in_sizes, int n_in,
                              void* d_out, int out_size)
{
    const float* Q  = (const float*)d_in[0];
    const float* Km = (const float*)d_in[1];
    const float* V  = (const float*)d_in[2];
    const float* Wo = (const float*)d_in[3];
    float* out = (float*)d_out;

    bf16 *Phi, *Plo, *Qhi, *Qlo, *Khi, *Klo, *Vthi, *Vtlo, *Wothi, *Wotlo, *O1hi, *O1lo;
    float* rowsum;
    cudaGetSymbolAddress((void**)&Phi,   g_Phi);
    cudaGetSymbolAddress((void**)&Plo,   g_Plo);
    cudaGetSymbolAddress((void**)&Qhi,   g_Qhi);
    cudaGetSymbolAddress((void**)&Qlo,   g_Qlo);
    cudaGetSymbolAddress((void**)&Khi,   g_Khi);
    cudaGetSymbolAddress((void**)&Klo,   g_Klo);
    cudaGetSymbolAddress((void**)&Vthi,  g_Vthi);
    cudaGetSymbolAddress((void**)&Vtlo,  g_Vtlo);
    cudaGetSymbolAddress((void**)&Wothi, g_Wothi);
    cudaGetSymbolAddress((void**)&Wotlo, g_Wotlo);
    cudaGetSymbolAddress((void**)&O1hi,  g_O1hi);
    cudaGetSymbolAddress((void**)&O1lo,  g_O1lo);
    cudaGetSymbolAddress((void**)&rowsum, g_rowsum);

    cudaFuncSetAttribute(gemm_bf16x3<EPI_PLAIN>,
                         cudaFuncAttributeMaxDynamicSharedMemorySize, GEMM_SMEM);
    cudaFuncSetAttribute(gemm_bf16x3<EPI_EXP>,
                         cudaFuncAttributeMaxDynamicSharedMemorySize, GEMM_SMEM);
    cudaFuncSetAttribute(gemm_bf16x3<EPI_SCALE>,
                         cudaFuncAttributeMaxDynamicSharedMemorySize, GEMM_SMEM);

    const float scale = 1.0f / sqrtf((float)KDIM);

    // prep
    zero_rowsum_kernel<<<SEQ / 256, 256>>>(rowsum);
    split_kernel<<<(SEQ * KDIM / 4) / 256, 256>>>(Q, Qhi, Qlo);
    split_kernel<<<(SEQ * KDIM / 4) / 256, 256>>>(Km, Khi, Klo);
    transpose_split_kernel<<<dim3(KDIM / 32, SEQ / 32), dim3(32, 8)>>>(V, Vthi, Vtlo, SEQ, KDIM);
    transpose_split_kernel<<<dim3(DDIM / 32, KDIM / 32), dim3(32, 8)>>>(Wo, Wothi, Wotlo, KDIM, DDIM);

    // 1) P = exp(scale * Q K^T), rowsum accumulated
    gemm_bf16x3<EPI_EXP><<<dim3(SEQ / BN, SEQ / BM), 256, GEMM_SMEM>>>(
        Qhi, Qlo, Khi, Klo, nullptr, Phi, Plo, rowsum, KDIM, SEQ, scale);
    // 2) O1 = (P V) / rowsum  -> bf16 hi/lo
    gemm_bf16x3<EPI_SCALE><<<dim3(KDIM / BN, SEQ / BM), 256, GEMM_SMEM>>>(
        Phi, Plo, Vthi, Vtlo, nullptr, O1hi, O1lo, rowsum, SEQ, KDIM, 1.0f);
    // 3) out = O1 Wo
    gemm_bf16x3<EPI_PLAIN><<<dim3(DDIM / BN, SEQ / BM), 256, GEMM_SMEM>>>(
        O1hi, O1lo, Wothi, Wotlo, out, nullptr, nullptr, nullptr, KDIM, DDIM, 1.0f);
}

// round 9
// speedup vs baseline: 2.0953x; 1.0672x over previous
#include <cuda_runtime.h>
#include <cuda_bf16.h>
#include <math.h>
#include <stdint.h>

#define SEQ   8192
#define KDIM  512
#define DDIM  512

typedef __nv_bfloat16 bf16;
typedef __nv_bfloat162 bf162;

// ---------------- scratch (__device__ globals; no allocation allowed) -------
__device__ bf16  g_Phi [(size_t)SEQ * SEQ];
__device__ bf16  g_Plo [(size_t)SEQ * SEQ];
__device__ bf16  g_Qhi [(size_t)SEQ * KDIM];
__device__ bf16  g_Qlo [(size_t)SEQ * KDIM];
__device__ bf16  g_Khi [(size_t)SEQ * KDIM];
__device__ bf16  g_Klo [(size_t)SEQ * KDIM];
__device__ bf16  g_Vthi[(size_t)KDIM * SEQ];
__device__ bf16  g_Vtlo[(size_t)KDIM * SEQ];
__device__ bf16  g_Wothi[(size_t)DDIM * KDIM];
__device__ bf16  g_Wotlo[(size_t)DDIM * KDIM];
__device__ bf16  g_O1hi[(size_t)SEQ * KDIM];
__device__ bf16  g_O1lo[(size_t)SEQ * KDIM];
__device__ float g_rowsum[SEQ];

// ---------------------------------------------------------------------------
// bf16x3 GEMM, mma.sync + cp.async:  C = A * B^T  (pre-split hi/lo operands)
// CTA 128x128, BK=64, 8 warps x (64x32), 3-stage cp.async, double-buffered
// ldmatrix fragments (ks+1 loads overlap ks MMAs).
// ---------------------------------------------------------------------------
#define BM 128
#define BN 128
#define BK 64
#define SKEW 72                           // bf16/row: 64 data + 8 pad
#define TILE_B (128 * SKEW * 2)           // 18432 bytes
#define OFF_AHI 0
#define OFF_ALO TILE_B
#define OFF_BHI (2 * TILE_B)
#define OFF_BLO (3 * TILE_B)
#define STAGE_B (4 * TILE_B)              // 73728
#define NSTAGE 3
#define GEMM_SMEM (NSTAGE * STAGE_B)      // 221184

#define EPI_PLAIN 0
#define EPI_EXP   1
#define EPI_SCALE 2

__device__ __forceinline__ uint32_t smem_u32(const void* p) {
    uint32_t a;
    asm("{ .reg .u64 t; cvta.to.shared.u64 t, %1; cvt.u32.u64 %0, t; }" : "=r"(a) : "l"(p));
    return a;
}
__device__ __forceinline__ void cpa16(uint32_t dst, const void* src) {
    asm volatile("cp.async.cg.shared.global [%0], [%1], 16;" :: "r"(dst), "l"(src));
}
__device__ __forceinline__ void ldsm4(uint32_t& r0, uint32_t& r1, uint32_t& r2,
                                      uint32_t& r3, uint32_t addr) {
    asm volatile("ldmatrix.sync.aligned.m8n8.x4.shared.b16 {%0,%1,%2,%3}, [%4];"
                 : "=r"(r0), "=r"(r1), "=r"(r2), "=r"(r3) : "r"(addr));
}
__device__ __forceinline__ void mma16816(float* d, const uint32_t* a, const uint32_t* b) {
    asm volatile(
        "mma.sync.aligned.m16n8k16.row.col.f32.bf16.bf16.f32 "
        "{%0,%1,%2,%3}, {%4,%5,%6,%7}, {%8,%9}, {%0,%1,%2,%3};"
        : "+f"(d[0]), "+f"(d[1]), "+f"(d[2]), "+f"(d[3])
        : "r"(a[0]), "r"(a[1]), "r"(a[2]), "r"(a[3]), "r"(b[0]), "r"(b[1]));
}

template <int EPI>
__global__ __launch_bounds__(256, 1) void gemm_bf16x3(
    const bf16* __restrict__ Ahi, const bf16* __restrict__ Alo,
    const bf16* __restrict__ Bhi, const bf16* __restrict__ Blo,
    float* __restrict__ Cf, bf16* __restrict__ Chi, bf16* __restrict__ Clo,
    float* __restrict__ rowsum, int K, int N, float alpha)
{
    extern __shared__ char sm[];
    const uint32_t smbase = smem_u32(sm);
    const int tid  = threadIdx.x;
    const int wid  = tid >> 5;
    const int lane = tid & 31;
    const int wm   = (wid >> 2) * 64;
    const int wn   = (wid & 3) * 32;

    const size_t aoff = (size_t)blockIdx.y * BM * K;
    const size_t boff = (size_t)blockIdx.x * BN * K;
    const bf16* Ah = Ahi + aoff;  const bf16* Al = Alo + aoff;
    const bf16* Bh = Bhi + boff;  const bf16* Bl = Blo + boff;

    float acc[4][4][4];
    #pragma unroll
    for (int i = 0; i < 4; i++)
        #pragma unroll
        for (int j = 0; j < 4; j++)
            #pragma unroll
            for (int r = 0; r < 4; r++) acc[i][j][r] = 0.0f;

    const int NC = K / BK;

    auto FILL = [&](int c, int s) {
        const uint32_t sb = smbase + (uint32_t)s * STAGE_B;
        #pragma unroll
        for (int i = 0; i < 4; i++) {
            const int idx = tid + i * 256;        // 0..1023
            const int row = idx >> 3;             // 0..127
            const int ch  = idx & 7;              // 16B chunk (8 per 128B row)
            const uint32_t d = (uint32_t)(row * SKEW + ch * 8) * 2;
            const size_t go = (size_t)row * K + (size_t)c * BK + ch * 8;
            cpa16(sb + OFF_AHI + d, Ah + go);
            cpa16(sb + OFF_ALO + d, Al + go);
            cpa16(sb + OFF_BHI + d, Bh + go);
            cpa16(sb + OFF_BLO + d, Bl + go);
        }
    };

    const int rA   = lane & 15;
    const int colS = (lane >> 4) << 3;

    // double-buffered fragments
    uint32_t ah[2][4][4], al[2][4][4], bh[2][4][2], bl[2][4][2];

    auto LOADFRAG = [&](int b, int ks, uint32_t base) {
        const int col = ks * 16 + colS;
        #pragma unroll
        for (int mi = 0; mi < 4; mi++) {
            const uint32_t ro = (uint32_t)((wm + mi * 16 + rA) * SKEW + col) * 2;
            ldsm4(ah[b][mi][0], ah[b][mi][1], ah[b][mi][2], ah[b][mi][3],
                  base + OFF_AHI + ro);
            ldsm4(al[b][mi][0], al[b][mi][1], al[b][mi][2], al[b][mi][3],
                  base + OFF_ALO + ro);
        }
        #pragma unroll
        for (int p = 0; p < 2; p++) {
            const uint32_t ro = (uint32_t)((wn + p * 16 + rA) * SKEW + col) * 2;
            uint32_t r0, r1, r2, r3;
            ldsm4(r0, r1, r2, r3, base + OFF_BHI + ro);
            bh[b][2 * p][0] = r0;     bh[b][2 * p][1] = r2;
            bh[b][2 * p + 1][0] = r1; bh[b][2 * p + 1][1] = r3;
            ldsm4(r0, r1, r2, r3, base + OFF_BLO + ro);
            bl[b][2 * p][0] = r0;     bl[b][2 * p][1] = r2;
            bl[b][2 * p + 1][0] = r1; bl[b][2 * p + 1][1] = r3;
        }
    };

    auto MMAS = [&](int b) {
        #pragma unroll
        for (int mi = 0; mi < 4; mi++)
            #pragma unroll
            for (int nj = 0; nj < 4; nj++) {
                mma16816(acc[mi][nj], ah[b][mi], bh[b][nj]);
                mma16816(acc[mi][nj], ah[b][mi], bl[b][nj]);
                mma16816(acc[mi][nj], al[b][mi], bh[b][nj]);
            }
    };

    // ---- 3-stage pipeline, 1 sync per chunk ----
    FILL(0, 0); asm volatile("cp.async.commit_group;");
    if (NC > 1) FILL(1, 1);
    asm volatile("cp.async.commit_group;");

    for (int c = 0; c < NC; c++) {
        asm volatile("cp.async.wait_group 1;");
        __syncthreads();
        // refill the stage whose reads completed at the barrier
        if (c + 2 < NC) FILL(c + 2, (c + 2) % NSTAGE);
        asm volatile("cp.async.commit_group;");

        const uint32_t base = smbase + (uint32_t)(c % NSTAGE) * STAGE_B;
        LOADFRAG(0, 0, base);
        #pragma unroll
        for (int ks = 0; ks < 4; ks++) {
            const int cur = ks & 1;
            if (ks < 3) LOADFRAG(cur ^ 1, ks + 1, base);
            MMAS(cur);
        }
    }

    // ---- epilogue ----
    #pragma unroll
    for (int mi = 0; mi < 4; mi++) {
        const int r0 = blockIdx.y * BM + wm + mi * 16 + (lane >> 2);
        float rs0 = 0.0f, rs1 = 0.0f;
        float inv0 = 1.0f, inv1 = 1.0f;
        if (EPI == EPI_SCALE) {
            inv0 = 1.0f / rowsum[r0];
            inv1 = 1.0f / rowsum[r0 + 8];
        }
        #pragma unroll
        for (int nj = 0; nj < 4; nj++) {
            const int col = blockIdx.x * BN + wn + nj * 8 + 2 * (lane & 3);
            if (EPI == EPI_PLAIN) {
                *(float2*)(Cf + (size_t)r0 * N + col) =
                    make_float2(acc[mi][nj][0], acc[mi][nj][1]);
                *(float2*)(Cf + (size_t)(r0 + 8) * N + col) =
                    make_float2(acc[mi][nj][2], acc[mi][nj][3]);
            } else if (EPI == EPI_EXP) {
                float e0 = __expf(alpha * acc[mi][nj][0]);
                float e1 = __expf(alpha * acc[mi][nj][1]);
                float e2 = __expf(alpha * acc[mi][nj][2]);
                float e3 = __expf(alpha * acc[mi][nj][3]);
                bf16 h0 = __float2bfloat16_rn(e0), h1 = __float2bfloat16_rn(e1);
                bf16 h2 = __float2bfloat16_rn(e2), h3 = __float2bfloat16_rn(e3);
                *(bf162*)(Chi + (size_t)r0 * N + col) = bf162(h0, h1);
                *(bf162*)(Chi + (size_t)(r0 + 8) * N + col) = bf162(h2, h3);
                *(bf162*)(Clo + (size_t)r0 * N + col) =
                    bf162(__float2bfloat16_rn(e0 - __bfloat162float(h0)),
                          __float2bfloat16_rn(e1 - __bfloat162float(h1)));
                *(bf162*)(Clo + (size_t)(r0 + 8) * N + col) =
                    bf162(__float2bfloat16_rn(e2 - __bfloat162float(h2)),
                          __float2bfloat16_rn(e3 - __bfloat162float(h3)));
                rs0 += e0 + e1;  rs1 += e2 + e3;
            } else {
                float v0 = acc[mi][nj][0] * inv0, v1 = acc[mi][nj][1] * inv0;
                float v2 = acc[mi][nj][2] * inv1, v3 = acc[mi][nj][3] * inv1;
                bf16 h0 = __float2bfloat16_rn(v0), h1 = __float2bfloat16_rn(v1);
                bf16 h2 = __float2bfloat16_rn(v2), h3 = __float2bfloat16_rn(v3);
                *(bf162*)(Chi + (size_t)r0 * N + col) = bf162(h0, h1);
                *(bf162*)(Chi + (size_t)(r0 + 8) * N + col) = bf162(h2, h3);
                *(bf162*)(Clo + (size_t)r0 * N + col) =
                    bf162(__float2bfloat16_rn(v0 - __bfloat162float(h0)),
                          __float2bfloat16_rn(v1 - __bfloat162float(h1)));
                *(bf162*)(Clo + (size_t)(r0 + 8) * N + col) =
                    bf162(__float2bfloat16_rn(v2 - __bfloat162float(h2)),
                          __float2bfloat16_rn(v3 - __bfloat162float(h3)));
            }
        }
        if (EPI == EPI_EXP) {
            rs0 += __shfl_xor_sync(0xffffffffu, rs0, 1);
            rs0 += __shfl_xor_sync(0xffffffffu, rs0, 2);
            rs1 += __shfl_xor_sync(0xffffffffu, rs1, 1);
            rs1 += __shfl_xor_sync(0xffffffffu, rs1, 2);
            if ((lane & 3) == 0) {
                atomicAdd(rowsum + r0, rs0);
                atomicAdd(rowsum + r0 + 8, rs1);
            }
        }
    }
}

// ---------------------------------------------------------------------------
__global__ __launch_bounds__(256) void split_kernel(
    const float* __restrict__ in, bf16* __restrict__ hi, bf16* __restrict__ lo)
{
    const size_t i = (size_t)blockIdx.x * 256 + threadIdx.x;
    float4 v = ((const float4*)in)[i];
    bf16 h0 = __float2bfloat16_rn(v.x), h1 = __float2bfloat16_rn(v.y);
    bf16 h2 = __float2bfloat16_rn(v.z), h3 = __float2bfloat16_rn(v.w);
    ((bf162*)hi)[2 * i]     = bf162(h0, h1);
    ((bf162*)hi)[2 * i + 1] = bf162(h2, h3);
    ((bf162*)lo)[2 * i] =
        bf162(__float2bfloat16_rn(v.x - __bfloat162float(h0)),
              __float2bfloat16_rn(v.y - __bfloat162float(h1)));
    ((bf162*)lo)[2 * i + 1] =
        bf162(__float2bfloat16_rn(v.z - __bfloat162float(h2)),
              __float2bfloat16_rn(v.w - __bfloat162float(h3)));
}

__global__ __launch_bounds__(256) void transpose_split_kernel(
    const float* __restrict__ in, bf16* __restrict__ ohi, bf16* __restrict__ olo,
    int R, int C)
{
    __shared__ float t[32][33];
    const int bx = blockIdx.x * 32;
    const int by = blockIdx.y * 32;
    #pragma unroll
    for (int j = threadIdx.y; j < 32; j += 8)
        t[j][threadIdx.x] = in[(size_t)(by + j) * C + bx + threadIdx.x];
    __syncthreads();
    #pragma unroll
    for (int j = threadIdx.y; j < 32; j += 8) {
        const float v = t[threadIdx.x][j];
        const size_t o = (size_t)(bx + j) * R + by + threadIdx.x;
        const bf16 h = __float2bfloat16_rn(v);
        ohi[o] = h;
        olo[o] = __float2bfloat16_rn(v - __bfloat162float(h));
    }
}

__global__ void zero_rowsum_kernel(float* __restrict__ rs)
{
    rs[blockIdx.x * 256 + threadIdx.x] = 0.0f;
}

// ---------------------------------------------------------------------------
extern "C" void kernel_launch(void* const* d_in, const int* in_sizes, int n_in,
                              void* d_out, int out_size)
{
    const float* Q  = (const float*)d_in[0];
    const float* Km = (const float*)d_in[1];
    const float* V  = (const float*)d_in[2];
    const float* Wo = (const float*)d_in[3];
    float* out = (float*)d_out;

    bf16 *Phi, *Plo, *Qhi, *Qlo, *Khi, *Klo, *Vthi, *Vtlo, *Wothi, *Wotlo, *O1hi, *O1lo;
    float* rowsum;
    cudaGetSymbolAddress((void**)&Phi,   g_Phi);
    cudaGetSymbolAddress((void**)&Plo,   g_Plo);
    cudaGetSymbolAddress((void**)&Qhi,   g_Qhi);
    cudaGetSymbolAddress((void**)&Qlo,   g_Qlo);
    cudaGetSymbolAddress((void**)&Khi,   g_Khi);
    cudaGetSymbolAddress((void**)&Klo,   g_Klo);
    cudaGetSymbolAddress((void**)&Vthi,  g_Vthi);
    cudaGetSymbolAddress((void**)&Vtlo,  g_Vtlo);
    cudaGetSymbolAddress((void**)&Wothi, g_Wothi);
    cudaGetSymbolAddress((void**)&Wotlo, g_Wotlo);
    cudaGetSymbolAddress((void**)&O1hi,  g_O1hi);
    cudaGetSymbolAddress((void**)&O1lo,  g_O1lo);
    cudaGetSymbolAddress((void**)&rowsum, g_rowsum);

    cudaFuncSetAttribute(gemm_bf16x3<EPI_PLAIN>,
                         cudaFuncAttributeMaxDynamicSharedMemorySize, GEMM_SMEM);
    cudaFuncSetAttribute(gemm_bf16x3<EPI_EXP>,
                         cudaFuncAttributeMaxDynamicSharedMemorySize, GEMM_SMEM);
    cudaFuncSetAttribute(gemm_bf16x3<EPI_SCALE>,
                         cudaFuncAttributeMaxDynamicSharedMemorySize, GEMM_SMEM);

    const float scale = 1.0f / sqrtf((float)KDIM);

    zero_rowsum_kernel<<<SEQ / 256, 256>>>(rowsum);
    split_kernel<<<(SEQ * KDIM / 4) / 256, 256>>>(Q, Qhi, Qlo);
    split_kernel<<<(SEQ * KDIM / 4) / 256, 256>>>(Km, Khi, Klo);
    transpose_split_kernel<<<dim3(KDIM / 32, SEQ / 32), dim3(32, 8)>>>(V, Vthi, Vtlo, SEQ, KDIM);
    transpose_split_kernel<<<dim3(DDIM / 32, KDIM / 32), dim3(32, 8)>>>(Wo, Wothi, Wotlo, KDIM, DDIM);

    // 1) P = exp(scale * Q K^T), rowsum accumulated
    gemm_bf16x3<EPI_EXP><<<dim3(SEQ / BN, SEQ / BM), 256, GEMM_SMEM>>>(
        Qhi, Qlo, Khi, Klo, nullptr, Phi, Plo, rowsum, KDIM, SEQ, scale);
    // 2) O1 = (P V) / rowsum
    gemm_bf16x3<EPI_SCALE><<<dim3(KDIM / BN, SEQ / BM), 256, GEMM_SMEM>>>(
        Phi, Plo, Vthi, Vtlo, nullptr, O1hi, O1lo, rowsum, SEQ, KDIM, 1.0f);
    // 3) out = O1 Wo
    gemm_bf16x3<EPI_PLAIN><<<dim3(DDIM / BN, SEQ / BM), 256, GEMM_SMEM>>>(
        O1hi, O1lo, Wothi, Wotlo, out, nullptr, nullptr, nullptr, KDIM, DDIM, 1.0f);
}

// round 12
// speedup vs baseline: 5.2628x; 2.5117x over previous
#include <cuda_runtime.h>
#include <cuda_fp16.h>
#include <math.h>
#include <stdint.h>

#define SEQ   8192
#define KDIM  512
#define DDIM  512

typedef __half fp16;

// ---------------- scratch (__device__ globals; no allocation allowed) -------
__device__ fp16  g_P  [(size_t)SEQ * SEQ];     // 128 MB exp(S) fp16
__device__ fp16  g_Qh [(size_t)SEQ * KDIM];
__device__ fp16  g_Kh [(size_t)SEQ * KDIM];
__device__ fp16  g_Vt [(size_t)KDIM * SEQ];    // V^T fp16
__device__ fp16  g_Wot[(size_t)DDIM * KDIM];   // Wo^T fp16
__device__ fp16  g_O1 [(size_t)SEQ * KDIM];
__device__ float g_rowsum[SEQ];

// ---------------------------------------------------------------------------
// fp16 GEMM, mma.sync + cp.async:  C = A * B^T   (A:[M,K], B:[N,K] fp16)
// fp32 accumulate. CTA 128x128, BK=64, 8 warps x (64x32), 4-stage cp.async,
// double-buffered ldmatrix fragments. (Resubmit of R10 — container died with
// no diagnostics; isolating infra flake vs artifact.)
// ---------------------------------------------------------------------------
#define BM 128
#define BN 128
#define BK 64
#define SKEW 72                           // fp16/row: 64 data + 8 pad
#define TILE_B (128 * SKEW * 2)           // 18432 bytes
#define OFF_A 0
#define OFF_B TILE_B
#define STAGE_B (2 * TILE_B)              // 36864
#define NSTAGE 4
#define GEMM_SMEM (NSTAGE * STAGE_B)      // 147456

#define EPI_PLAIN 0
#define EPI_EXP   1
#define EPI_SCALE 2

__device__ __forceinline__ uint32_t smem_u32(const void* p) {
    uint32_t a;
    asm("{ .reg .u64 t; cvta.to.shared.u64 t, %1; cvt.u32.u64 %0, t; }" : "=r"(a) : "l"(p));
    return a;
}
__device__ __forceinline__ void cpa16(uint32_t dst, const void* src) {
    asm volatile("cp.async.cg.shared.global [%0], [%1], 16;" :: "r"(dst), "l"(src));
}
__device__ __forceinline__ void ldsm4(uint32_t& r0, uint32_t& r1, uint32_t& r2,
                                      uint32_t& r3, uint32_t addr) {
    asm volatile("ldmatrix.sync.aligned.m8n8.x4.shared.b16 {%0,%1,%2,%3}, [%4];"
                 : "=r"(r0), "=r"(r1), "=r"(r2), "=r"(r3) : "r"(addr));
}
__device__ __forceinline__ void mma16816(float* d, const uint32_t* a, const uint32_t* b) {
    asm volatile(
        "mma.sync.aligned.m16n8k16.row.col.f32.f16.f16.f32 "
        "{%0,%1,%2,%3}, {%4,%5,%6,%7}, {%8,%9}, {%0,%1,%2,%3};"
        : "+f"(d[0]), "+f"(d[1]), "+f"(d[2]), "+f"(d[3])
        : "r"(a[0]), "r"(a[1]), "r"(a[2]), "r"(a[3]), "r"(b[0]), "r"(b[1]));
}

template <int EPI>
__global__ __launch_bounds__(256, 1) void gemm_fp16(
    const fp16* __restrict__ A, const fp16* __restrict__ B,
    float* __restrict__ Cf, fp16* __restrict__ Ch,
    float* __restrict__ rowsum, int K, int N, float alpha)
{
    extern __shared__ char sm[];
    const uint32_t smbase = smem_u32(sm);
    const int tid  = threadIdx.x;
    const int wid  = tid >> 5;
    const int lane = tid & 31;
    const int wm   = (wid >> 2) * 64;
    const int wn   = (wid & 3) * 32;

    const fp16* Ab = A + (size_t)blockIdx.y * BM * K;
    const fp16* Bb = B + (size_t)blockIdx.x * BN * K;

    float acc[4][4][4];
    #pragma unroll
    for (int i = 0; i < 4; i++)
        #pragma unroll
        for (int j = 0; j < 4; j++)
            #pragma unroll
            for (int r = 0; r < 4; r++) acc[i][j][r] = 0.0f;

    const int NC = K / BK;

    auto FILL = [&](int c, int s) {
        const uint32_t sb = smbase + (uint32_t)s * STAGE_B;
        #pragma unroll
        for (int i = 0; i < 4; i++) {
            const int idx = tid + i * 256;        // 0..1023
            const int row = idx >> 3;             // 0..127
            const int ch  = idx & 7;              // 16B chunk (8 per 128B row)
            const uint32_t d = (uint32_t)(row * SKEW + ch * 8) * 2;
            const size_t go = (size_t)row * K + (size_t)c * BK + ch * 8;
            cpa16(sb + OFF_A + d, Ab + go);
            cpa16(sb + OFF_B + d, Bb + go);
        }
    };

    const int rA   = lane & 15;
    const int colS = (lane >> 4) << 3;

    uint32_t ah[2][4][4], bh[2][4][2];

    auto LOADFRAG = [&](int b, int ks, uint32_t base) {
        const int col = ks * 16 + colS;
        #pragma unroll
        for (int mi = 0; mi < 4; mi++) {
            const uint32_t ro = (uint32_t)((wm + mi * 16 + rA) * SKEW + col) * 2;
            ldsm4(ah[b][mi][0], ah[b][mi][1], ah[b][mi][2], ah[b][mi][3],
                  base + OFF_A + ro);
        }
        #pragma unroll
        for (int p = 0; p < 2; p++) {
            const uint32_t ro = (uint32_t)((wn + p * 16 + rA) * SKEW + col) * 2;
            uint32_t r0, r1, r2, r3;
            ldsm4(r0, r1, r2, r3, base + OFF_B + ro);
            bh[b][2 * p][0] = r0;     bh[b][2 * p][1] = r2;
            bh[b][2 * p + 1][0] = r1; bh[b][2 * p + 1][1] = r3;
        }
    };

    auto MMAS = [&](int b) {
        #pragma unroll
        for (int mi = 0; mi < 4; mi++)
            #pragma unroll
            for (int nj = 0; nj < 4; nj++)
                mma16816(acc[mi][nj], ah[b][mi], bh[b][nj]);
    };

    // ---- 4-stage pipeline, 1 sync per chunk ----
    FILL(0, 0); asm volatile("cp.async.commit_group;");
    if (NC > 1) FILL(1, 1);
    asm volatile("cp.async.commit_group;");
    if (NC > 2) FILL(2, 2);
    asm volatile("cp.async.commit_group;");

    for (int c = 0; c < NC; c++) {
        asm volatile("cp.async.wait_group 2;");
        __syncthreads();
        if (c + 3 < NC) FILL(c + 3, (c + 3) & 3);
        asm volatile("cp.async.commit_group;");

        const uint32_t base = smbase + (uint32_t)(c & 3) * STAGE_B;
        LOADFRAG(0, 0, base);
        #pragma unroll
        for (int ks = 0; ks < 4; ks++) {
            const int cur = ks & 1;
            if (ks < 3) LOADFRAG(cur ^ 1, ks + 1, base);
            MMAS(cur);
        }
    }

    // ---- epilogue ----
    #pragma unroll
    for (int mi = 0; mi < 4; mi++) {
        const int r0 = blockIdx.y * BM + wm + mi * 16 + (lane >> 2);
        float rs0 = 0.0f, rs1 = 0.0f;
        float inv0 = 1.0f, inv1 = 1.0f;
        if (EPI == EPI_SCALE) {
            inv0 = 1.0f / rowsum[r0];
            inv1 = 1.0f / rowsum[r0 + 8];
        }
        #pragma unroll
        for (int nj = 0; nj < 4; nj++) {
            const int col = blockIdx.x * BN + wn + nj * 8 + 2 * (lane & 3);
            if (EPI == EPI_PLAIN) {
                *(float2*)(Cf + (size_t)r0 * N + col) =
                    make_float2(acc[mi][nj][0], acc[mi][nj][1]);
                *(float2*)(Cf + (size_t)(r0 + 8) * N + col) =
                    make_float2(acc[mi][nj][2], acc[mi][nj][3]);
            } else if (EPI == EPI_EXP) {
                float e0 = __expf(alpha * acc[mi][nj][0]);
                float e1 = __expf(alpha * acc[mi][nj][1]);
                float e2 = __expf(alpha * acc[mi][nj][2]);
                float e3 = __expf(alpha * acc[mi][nj][3]);
                *(__half2*)(Ch + (size_t)r0 * N + col) =
                    __floats2half2_rn(e0, e1);
                *(__half2*)(Ch + (size_t)(r0 + 8) * N + col) =
                    __floats2half2_rn(e2, e3);
                rs0 += e0 + e1;  rs1 += e2 + e3;
            } else { // EPI_SCALE
                *(__half2*)(Ch + (size_t)r0 * N + col) =
                    __floats2half2_rn(acc[mi][nj][0] * inv0, acc[mi][nj][1] * inv0);
                *(__half2*)(Ch + (size_t)(r0 + 8) * N + col) =
                    __floats2half2_rn(acc[mi][nj][2] * inv1, acc[mi][nj][3] * inv1);
            }
        }
        if (EPI == EPI_EXP) {
            rs0 += __shfl_xor_sync(0xffffffffu, rs0, 1);
            rs0 += __shfl_xor_sync(0xffffffffu, rs0, 2);
            rs1 += __shfl_xor_sync(0xffffffffu, rs1, 1);
            rs1 += __shfl_xor_sync(0xffffffffu, rs1, 2);
            if ((lane & 3) == 0) {
                atomicAdd(rowsum + r0, rs0);
                atomicAdd(rowsum + r0 + 8, rs1);
            }
        }
    }
}

// ---------------------------------------------------------------------------
// fp32 -> fp16 convert (vectorized: 4 elems/thread)
// ---------------------------------------------------------------------------
__global__ __launch_bounds__(256) void cvt_kernel(
    const float* __restrict__ in, fp16* __restrict__ out)
{
    const size_t i = (size_t)blockIdx.x * 256 + threadIdx.x;
    float4 v = ((const float4*)in)[i];
    ((__half2*)out)[2 * i]     = __floats2half2_rn(v.x, v.y);
    ((__half2*)out)[2 * i + 1] = __floats2half2_rn(v.z, v.w);
}

// ---------------------------------------------------------------------------
// Transpose + convert: in [R,C] fp32 -> out^T [C,R] fp16
// ---------------------------------------------------------------------------
__global__ __launch_bounds__(256) void transpose_cvt_kernel(
    const float* __restrict__ in, fp16* __restrict__ out, int R, int C)
{
    __shared__ float t[32][33];
    const int bx = blockIdx.x * 32;
    const int by = blockIdx.y * 32;
    #pragma unroll
    for (int j = threadIdx.y; j < 32; j += 8)
        t[j][threadIdx.x] = in[(size_t)(by + j) * C + bx + threadIdx.x];
    __syncthreads();
    #pragma unroll
    for (int j = threadIdx.y; j < 32; j += 8)
        out[(size_t)(bx + j) * R + by + threadIdx.x] =
            __float2half_rn(t[threadIdx.x][j]);
}

__global__ void zero_rowsum_kernel(float* __restrict__ rs)
{
    rs[blockIdx.x * 256 + threadIdx.x] = 0.0f;
}

// ---------------------------------------------------------------------------
extern "C" void kernel_launch(void* const* d_in, const int* in_sizes, int n_in,
                              void* d_out, int out_size)
{
    const float* Q  = (const float*)d_in[0];
    const float* Km = (const float*)d_in[1];
    const float* V  = (const float*)d_in[2];
    const float* Wo = (const float*)d_in[3];
    float* out = (float*)d_out;

    fp16 *P, *Qh, *Kh, *Vt, *Wot, *O1;
    float* rowsum;
    cudaGetSymbolAddress((void**)&P,   g_P);
    cudaGetSymbolAddress((void**)&Qh,  g_Qh);
    cudaGetSymbolAddress((void**)&Kh,  g_Kh);
    cudaGetSymbolAddress((void**)&Vt,  g_Vt);
    cudaGetSymbolAddress((void**)&Wot, g_Wot);
    cudaGetSymbolAddress((void**)&O1,  g_O1);
    cudaGetSymbolAddress((void**)&rowsum, g_rowsum);

    cudaFuncSetAttribute(gemm_fp16<EPI_PLAIN>,
                         cudaFuncAttributeMaxDynamicSharedMemorySize, GEMM_SMEM);
    cudaFuncSetAttribute(gemm_fp16<EPI_EXP>,
                         cudaFuncAttributeMaxDynamicSharedMemorySize, GEMM_SMEM);
    cudaFuncSetAttribute(gemm_fp16<EPI_SCALE>,
                         cudaFuncAttributeMaxDynamicSharedMemorySize, GEMM_SMEM);

    const float scale = 1.0f / sqrtf((float)KDIM);

    zero_rowsum_kernel<<<SEQ / 256, 256>>>(rowsum);
    cvt_kernel<<<(SEQ * KDIM / 4) / 256, 256>>>(Q, Qh);
    cvt_kernel<<<(SEQ * KDIM / 4) / 256, 256>>>(Km, Kh);
    transpose_cvt_kernel<<<dim3(KDIM / 32, SEQ / 32), dim3(32, 8)>>>(V, Vt, SEQ, KDIM);
    transpose_cvt_kernel<<<dim3(DDIM / 32, KDIM / 32), dim3(32, 8)>>>(Wo, Wot, KDIM, DDIM);

    // 1) P = exp(scale * Q K^T) (fp16), rowsum accumulated
    gemm_fp16<EPI_EXP><<<dim3(SEQ / BN, SEQ / BM), 256, GEMM_SMEM>>>(
        Qh, Kh, nullptr, P, rowsum, KDIM, SEQ, scale);
    // 2) O1 = (P V) / rowsum  (fp16)
    gemm_fp16<EPI_SCALE><<<dim3(KDIM / BN, SEQ / BM), 256, GEMM_SMEM>>>(
        P, Vt, nullptr, O1, rowsum, SEQ, KDIM, 1.0f);
    // 3) out = O1 Wo  (fp32 out)
    gemm_fp16<EPI_PLAIN><<<dim3(DDIM / BN, SEQ / BM), 256, GEMM_SMEM>>>(
        O1, Wot, out, nullptr, nullptr, KDIM, DDIM, 1.0f);
}

// round 13
// speedup vs baseline: 6.0053x; 1.1411x over previous
#include <cuda_runtime.h>
#include <cuda_fp16.h>
#include <math.h>
#include <stdint.h>

#define SEQ   8192
#define KDIM  512
#define DDIM  512

typedef __half fp16;

// ---------------- scratch (__device__ globals; no allocation allowed) -------
__device__ fp16  g_P  [(size_t)SEQ * SEQ];     // 128 MB exp(S) fp16
__device__ fp16  g_Qh [(size_t)SEQ * KDIM];
__device__ fp16  g_Kh [(size_t)SEQ * KDIM];
__device__ fp16  g_Vt [(size_t)KDIM * SEQ];    // V^T fp16
__device__ fp16  g_Wot[(size_t)DDIM * KDIM];   // Wo^T fp16
__device__ fp16  g_O1 [(size_t)SEQ * KDIM];
__device__ float g_rowsum[SEQ];

// ---------------------------------------------------------------------------
// fp16 GEMM, mma.sync + cp.async:  C = A * B^T   (A:[M,K], B:[N,K] fp16)
// fp32 accumulate. CTA 128x128, BK=64, 8 warps x (64x32).
// R13: 2-stage smem + __launch_bounds__(256,2) -> 2 CTAs/SM. Cross-CTA overlap
// hides prologue/epilogue and ldsm latency (fragments single-buffered to fit
// 128 regs/thread).
// ---------------------------------------------------------------------------
#define BM 128
#define BN 128
#define BK 64
#define SKEW 72                           // fp16/row: 64 data + 8 pad
#define TILE_B (128 * SKEW * 2)           // 18432 bytes
#define OFF_A 0
#define OFF_B TILE_B
#define STAGE_B (2 * TILE_B)              // 36864
#define NSTAGE 2
#define GEMM_SMEM (NSTAGE * STAGE_B)      // 73728 -> 2 CTAs/SM

#define EPI_PLAIN 0
#define EPI_EXP   1
#define EPI_SCALE 2

__device__ __forceinline__ uint32_t smem_u32(const void* p) {
    uint32_t a;
    asm("{ .reg .u64 t; cvta.to.shared.u64 t, %1; cvt.u32.u64 %0, t; }" : "=r"(a) : "l"(p));
    return a;
}
__device__ __forceinline__ void cpa16(uint32_t dst, const void* src) {
    asm volatile("cp.async.cg.shared.global [%0], [%1], 16;" :: "r"(dst), "l"(src));
}
__device__ __forceinline__ void ldsm4(uint32_t& r0, uint32_t& r1, uint32_t& r2,
                                      uint32_t& r3, uint32_t addr) {
    asm volatile("ldmatrix.sync.aligned.m8n8.x4.shared.b16 {%0,%1,%2,%3}, [%4];"
                 : "=r"(r0), "=r"(r1), "=r"(r2), "=r"(r3) : "r"(addr));
}
__device__ __forceinline__ void mma16816(float* d, const uint32_t* a, const uint32_t* b) {
    asm volatile(
        "mma.sync.aligned.m16n8k16.row.col.f32.f16.f16.f32 "
        "{%0,%1,%2,%3}, {%4,%5,%6,%7}, {%8,%9}, {%0,%1,%2,%3};"
        : "+f"(d[0]), "+f"(d[1]), "+f"(d[2]), "+f"(d[3])
        : "r"(a[0]), "r"(a[1]), "r"(a[2]), "r"(a[3]), "r"(b[0]), "r"(b[1]));
}

template <int EPI>
__global__ __launch_bounds__(256, 2) void gemm_fp16(
    const fp16* __restrict__ A, const fp16* __restrict__ B,
    float* __restrict__ Cf, fp16* __restrict__ Ch,
    float* __restrict__ rowsum, int K, int N, float alpha)
{
    extern __shared__ char sm[];
    const uint32_t smbase = smem_u32(sm);
    const int tid  = threadIdx.x;
    const int wid  = tid >> 5;
    const int lane = tid & 31;
    const int wm   = (wid >> 2) * 64;
    const int wn   = (wid & 3) * 32;

    const fp16* Ab = A + (size_t)blockIdx.y * BM * K;
    const fp16* Bb = B + (size_t)blockIdx.x * BN * K;

    float acc[4][4][4];
    #pragma unroll
    for (int i = 0; i < 4; i++)
        #pragma unroll
        for (int j = 0; j < 4; j++)
            #pragma unroll
            for (int r = 0; r < 4; r++) acc[i][j][r] = 0.0f;

    const int NC = K / BK;

    auto FILL = [&](int c, int s) {
        const uint32_t sb = smbase + (uint32_t)s * STAGE_B;
        #pragma unroll
        for (int i = 0; i < 4; i++) {
            const int idx = tid + i * 256;        // 0..1023
            const int row = idx >> 3;             // 0..127
            const int ch  = idx & 7;              // 16B chunk (8 per 128B row)
            const uint32_t d = (uint32_t)(row * SKEW + ch * 8) * 2;
            const size_t go = (size_t)row * K + (size_t)c * BK + ch * 8;
            cpa16(sb + OFF_A + d, Ab + go);
            cpa16(sb + OFF_B + d, Bb + go);
        }
    };

    const int rA   = lane & 15;
    const int colS = (lane >> 4) << 3;

    // single-buffered fragments (keeps regs <= 128 for occupancy 2)
    uint32_t ah[4][4], bh[4][2];

    auto LOADFRAG = [&](int ks, uint32_t base) {
        const int col = ks * 16 + colS;
        #pragma unroll
        for (int mi = 0; mi < 4; mi++) {
            const uint32_t ro = (uint32_t)((wm + mi * 16 + rA) * SKEW + col) * 2;
            ldsm4(ah[mi][0], ah[mi][1], ah[mi][2], ah[mi][3], base + OFF_A + ro);
        }
        #pragma unroll
        for (int p = 0; p < 2; p++) {
            const uint32_t ro = (uint32_t)((wn + p * 16 + rA) * SKEW + col) * 2;
            uint32_t r0, r1, r2, r3;
            ldsm4(r0, r1, r2, r3, base + OFF_B + ro);
            bh[2 * p][0] = r0;     bh[2 * p][1] = r2;
            bh[2 * p + 1][0] = r1; bh[2 * p + 1][1] = r3;
        }
    };

    auto MMAS = [&]() {
        #pragma unroll
        for (int mi = 0; mi < 4; mi++)
            #pragma unroll
            for (int nj = 0; nj < 4; nj++)
                mma16816(acc[mi][nj], ah[mi], bh[nj]);
    };

    // ---- 2-stage pipeline; fill of c+2 issues after compute of c ----
    FILL(0, 0); asm volatile("cp.async.commit_group;");
    if (NC > 1) FILL(1, 1);
    asm volatile("cp.async.commit_group;");

    for (int c = 0; c < NC; c++) {
        asm volatile("cp.async.wait_group 1;");
        __syncthreads();                              // stage c ready
        const uint32_t base = smbase + (uint32_t)(c & 1) * STAGE_B;
        #pragma unroll
        for (int ks = 0; ks < 4; ks++) {
            LOADFRAG(ks, base);
            MMAS();
        }
        __syncthreads();                              // all warps done reading stage
        if (c + 2 < NC) FILL(c + 2, c & 1);
        asm volatile("cp.async.commit_group;");       // commit every iter (keeps numbering)
    }

    // ---- epilogue ----
    #pragma unroll
    for (int mi = 0; mi < 4; mi++) {
        const int r0 = blockIdx.y * BM + wm + mi * 16 + (lane >> 2);
        float rs0 = 0.0f, rs1 = 0.0f;
        float inv0 = 1.0f, inv1 = 1.0f;
        if (EPI == EPI_SCALE) {
            inv0 = 1.0f / rowsum[r0];
            inv1 = 1.0f / rowsum[r0 + 8];
        }
        #pragma unroll
        for (int nj = 0; nj < 4; nj++) {
            const int col = blockIdx.x * BN + wn + nj * 8 + 2 * (lane & 3);
            if (EPI == EPI_PLAIN) {
                *(float2*)(Cf + (size_t)r0 * N + col) =
                    make_float2(acc[mi][nj][0], acc[mi][nj][1]);
                *(float2*)(Cf + (size_t)(r0 + 8) * N + col) =
                    make_float2(acc[mi][nj][2], acc[mi][nj][3]);
            } else if (EPI == EPI_EXP) {
                float e0 = __expf(alpha * acc[mi][nj][0]);
                float e1 = __expf(alpha * acc[mi][nj][1]);
                float e2 = __expf(alpha * acc[mi][nj][2]);
                float e3 = __expf(alpha * acc[mi][nj][3]);
                *(__half2*)(Ch + (size_t)r0 * N + col) =
                    __floats2half2_rn(e0, e1);
                *(__half2*)(Ch + (size_t)(r0 + 8) * N + col) =
                    __floats2half2_rn(e2, e3);
                rs0 += e0 + e1;  rs1 += e2 + e3;
            } else { // EPI_SCALE
                *(__half2*)(Ch + (size_t)r0 * N + col) =
                    __floats2half2_rn(acc[mi][nj][0] * inv0, acc[mi][nj][1] * inv0);
                *(__half2*)(Ch + (size_t)(r0 + 8) * N + col) =
                    __floats2half2_rn(acc[mi][nj][2] * inv1, acc[mi][nj][3] * inv1);
            }
        }
        if (EPI == EPI_EXP) {
            rs0 += __shfl_xor_sync(0xffffffffu, rs0, 1);
            rs0 += __shfl_xor_sync(0xffffffffu, rs0, 2);
            rs1 += __shfl_xor_sync(0xffffffffu, rs1, 1);
            rs1 += __shfl_xor_sync(0xffffffffu, rs1, 2);
            if ((lane & 3) == 0) {
                atomicAdd(rowsum + r0, rs0);
                atomicAdd(rowsum + r0 + 8, rs1);
            }
        }
    }
}

// ---------------------------------------------------------------------------
// fp32 -> fp16 convert (vectorized: 4 elems/thread)
// ---------------------------------------------------------------------------
__global__ __launch_bounds__(256) void cvt_kernel(
    const float* __restrict__ in, fp16* __restrict__ out)
{
    const size_t i = (size_t)blockIdx.x * 256 + threadIdx.x;
    float4 v = ((const float4*)in)[i];
    ((__half2*)out)[2 * i]     = __floats2half2_rn(v.x, v.y);
    ((__half2*)out)[2 * i + 1] = __floats2half2_rn(v.z, v.w);
}

// ---------------------------------------------------------------------------
// Transpose + convert: in [R,C] fp32 -> out^T [C,R] fp16
// ---------------------------------------------------------------------------
__global__ __launch_bounds__(256) void transpose_cvt_kernel(
    const float* __restrict__ in, fp16* __restrict__ out, int R, int C)
{
    __shared__ float t[32][33];
    const int bx = blockIdx.x * 32;
    const int by = blockIdx.y * 32;
    #pragma unroll
    for (int j = threadIdx.y; j < 32; j += 8)
        t[j][threadIdx.x] = in[(size_t)(by + j) * C + bx + threadIdx.x];
    __syncthreads();
    #pragma unroll
    for (int j = threadIdx.y; j < 32; j += 8)
        out[(size_t)(bx + j) * R + by + threadIdx.x] =
            __float2half_rn(t[threadIdx.x][j]);
}

__global__ void zero_rowsum_kernel(float* __restrict__ rs)
{
    rs[blockIdx.x * 256 + threadIdx.x] = 0.0f;
}

// ---------------------------------------------------------------------------
extern "C" void kernel_launch(void* const* d_in, const int* in_sizes, int n_in,
                              void* d_out, int out_size)
{
    const float* Q  = (const float*)d_in[0];
    const float* Km = (const float*)d_in[1];
    const float* V  = (const float*)d_in[2];
    const float* Wo = (const float*)d_in[3];
    float* out = (float*)d_out;

    fp16 *P, *Qh, *Kh, *Vt, *Wot, *O1;
    float* rowsum;
    cudaGetSymbolAddress((void**)&P,   g_P);
    cudaGetSymbolAddress((void**)&Qh,  g_Qh);
    cudaGetSymbolAddress((void**)&Kh,  g_Kh);
    cudaGetSymbolAddress((void**)&Vt,  g_Vt);
    cudaGetSymbolAddress((void**)&Wot, g_Wot);
    cudaGetSymbolAddress((void**)&O1,  g_O1);
    cudaGetSymbolAddress((void**)&rowsum, g_rowsum);

    cudaFuncSetAttribute(gemm_fp16<EPI_PLAIN>,
                         cudaFuncAttributeMaxDynamicSharedMemorySize, GEMM_SMEM);
    cudaFuncSetAttribute(gemm_fp16<EPI_EXP>,
                         cudaFuncAttributeMaxDynamicSharedMemorySize, GEMM_SMEM);
    cudaFuncSetAttribute(gemm_fp16<EPI_SCALE>,
                         cudaFuncAttributeMaxDynamicSharedMemorySize, GEMM_SMEM);

    const float scale = 1.0f / sqrtf((float)KDIM);

    zero_rowsum_kernel<<<SEQ / 256, 256>>>(rowsum);
    cvt_kernel<<<(SEQ * KDIM / 4) / 256, 256>>>(Q, Qh);
    cvt_kernel<<<(SEQ * KDIM / 4) / 256, 256>>>(Km, Kh);
    transpose_cvt_kernel<<<dim3(KDIM / 32, SEQ / 32), dim3(32, 8)>>>(V, Vt, SEQ, KDIM);
    transpose_cvt_kernel<<<dim3(DDIM / 32, KDIM / 32), dim3(32, 8)>>>(Wo, Wot, KDIM, DDIM);

    // 1) P = exp(scale * Q K^T) (fp16), rowsum accumulated
    gemm_fp16<EPI_EXP><<<dim3(SEQ / BN, SEQ / BM), 256, GEMM_SMEM>>>(
        Qh, Kh, nullptr, P, rowsum, KDIM, SEQ, scale);
    // 2) O1 = (P V) / rowsum  (fp16)
    gemm_fp16<EPI_SCALE><<<dim3(KDIM / BN, SEQ / BM), 256, GEMM_SMEM>>>(
        P, Vt, nullptr, O1, rowsum, SEQ, KDIM, 1.0f);
    // 3) out = O1 Wo  (fp32 out)
    gemm_fp16<EPI_PLAIN><<<dim3(DDIM / BN, SEQ / BM), 256, GEMM_SMEM>>>(
        O1, Wot, out, nullptr, nullptr, KDIM, DDIM, 1.0f);
}